// round 4
// baseline (speedup 1.0000x reference)
#include <cuda_runtime.h>

#define Tv 512
#define ROWW 60   // floats per smem row: 56 data + 4 pad (240B, 16B-aligned)

typedef unsigned long long u64;

__device__ __forceinline__ u64 PK(float a, float b) {
    u64 r; asm("mov.b64 %0,{%1,%2};" : "=l"(r) : "r"(__float_as_uint(a)), "r"(__float_as_uint(b))); return r;
}
__device__ __forceinline__ void UPK(u64 v, float& a, float& b) {
    unsigned x, y; asm("mov.b64 {%0,%1},%2;" : "=r"(x), "=r"(y) : "l"(v));
    a = __uint_as_float(x); b = __uint_as_float(y);
}
__device__ __forceinline__ u64 FMA2(u64 a, u64 b, u64 c) {
    u64 d; asm("fma.rn.f32x2 %0,%1,%2,%3;" : "=l"(d) : "l"(a), "l"(b), "l"(c)); return d;
}
__device__ __forceinline__ u64 MUL2(u64 a, u64 b) {
    u64 d; asm("mul.rn.f32x2 %0,%1,%2;" : "=l"(d) : "l"(a), "l"(b)); return d;
}
__device__ __forceinline__ u64 ADD2(u64 a, u64 b) {
    u64 d; asm("add.rn.f32x2 %0,%1,%2;" : "=l"(d) : "l"(a), "l"(b)); return d;
}
__device__ __forceinline__ void cpa16(float* dst, const void* src) {
    unsigned d = (unsigned)__cvta_generic_to_shared(dst);
    asm volatile("cp.async.cg.shared.global [%0], [%1], 16;" :: "r"(d), "l"(src));
}
#define CP_COMMIT() asm volatile("cp.async.commit_group;")
#define CP_WAIT2()  asm volatile("cp.async.wait_group 2;")

__global__ void __launch_bounds__(64, 1)
crf_fwd_kernel(const float* __restrict__ em,
               const int* __restrict__ labels,
               const int* __restrict__ mask,
               const float* __restrict__ startT,
               const float* __restrict__ endT,
               const float* __restrict__ trans,
               float* __restrict__ out)
{
    __shared__ float sm[2][3][32 * ROWW];
    __shared__ float sTrans[49];

    const int tid  = threadIdx.x;
    const int wid  = tid >> 5;
    const int lane = tid & 31;

    for (int i = tid; i < 49; i += 64) sTrans[i] = trans[i];
    __syncthreads();

    const int b = blockIdx.x * 64 + tid;
    const float* ebw = em + (size_t)(blockIdx.x * 64 + wid * 32) * (Tv * 7);
    const int4* lb4 = (const int4*)(labels + (size_t)b * Tv);
    const int4* mb4 = (const int4*)(mask + (size_t)b * Tv);

    // exp(transitions) in registers: packed pairs for cols 0-5, scalar col 6
    u64 EP[7][3]; float E6[7];
#pragma unroll
    for (int i = 0; i < 7; i++) {
        float e0 = __expf(__ldg(&trans[i*7+0])), e1 = __expf(__ldg(&trans[i*7+1]));
        float e2 = __expf(__ldg(&trans[i*7+2])), e3 = __expf(__ldg(&trans[i*7+3]));
        float e4 = __expf(__ldg(&trans[i*7+4])), e5 = __expf(__ldg(&trans[i*7+5]));
        EP[i][0] = PK(e0,e1); EP[i][1] = PK(e2,e3); EP[i][2] = PK(e4,e5);
        E6[i] = __expf(__ldg(&trans[i*7+6]));
    }

#define STAGE(MM) do { \
    float* _base = &sm[wid][(MM) % 3][0]; \
    const float* _g = ebw + (MM) * 56; \
    _Pragma("unroll") \
    for (int i = 0; i < 14; i++) { \
        int idx = i * 32 + lane; \
        int r = (idx * 4682) >> 16;     /* exact /14 for idx<448 */ \
        int c = idx - r * 14; \
        cpa16(_base + r * ROWW + c * 4, _g + (size_t)r * (Tv*7) + c * 4); \
    } \
    CP_COMMIT(); } while (0)

    u64 p01, p23, p45; float p6;
    int xsum = 0;
    float num;
    int prev;

    const float* myrow0 = &sm[wid][0][lane * ROWW];
    const float* myrow1 = &sm[wid][1][lane * ROWW];
    const float* myrow2 = &sm[wid][2][lane * ROWW];

    // one step: xe -> 7 exp'd emissions, rowraw -> same 7 raw (smem) for numerator
    auto STEP = [&](const float* xe, const float* rowraw, int L, int M) {
        int Lc = L < 0 ? 0 : L;
        float v = sTrans[prev * 7 + Lc] + rowraw[Lc];   // off critical path
        num += M ? v : 0.0f;
        prev = M ? Lc : prev;
        float a0,a1,a2,a3,a4,a5;
        UPK(p01,a0,a1); UPK(p23,a2,a3); UPK(p45,a4,a5);
        u64 b0 = PK(a0,a0), b1 = PK(a1,a1), b2 = PK(a2,a2), b3 = PK(a3,a3);
        u64 b4 = PK(a4,a4), b5 = PK(a5,a5), b6 = PK(p6,p6);
        // two independent accumulation chains per column pair (depth 4 vs 7)
        u64 qA01 = MUL2(b0,EP[0][0]); u64 qB01 = MUL2(b1,EP[1][0]);
        u64 qA23 = MUL2(b0,EP[0][1]); u64 qB23 = MUL2(b1,EP[1][1]);
        u64 qA45 = MUL2(b0,EP[0][2]); u64 qB45 = MUL2(b1,EP[1][2]);
        float qA6 = a0*E6[0];         float qB6 = a1*E6[1];
        qA01 = FMA2(b2,EP[2][0],qA01); qB01 = FMA2(b3,EP[3][0],qB01);
        qA23 = FMA2(b2,EP[2][1],qA23); qB23 = FMA2(b3,EP[3][1],qB23);
        qA45 = FMA2(b2,EP[2][2],qA45); qB45 = FMA2(b3,EP[3][2],qB45);
        qA6  = fmaf(a2,E6[2],qA6);     qB6  = fmaf(a3,E6[3],qB6);
        qA01 = FMA2(b4,EP[4][0],qA01); qB01 = FMA2(b5,EP[5][0],qB01);
        qA23 = FMA2(b4,EP[4][1],qA23); qB23 = FMA2(b5,EP[5][1],qB23);
        qA45 = FMA2(b4,EP[4][2],qA45); qB45 = FMA2(b5,EP[5][2],qB45);
        qA6  = fmaf(a4,E6[4],qA6);     qB6  = fmaf(a5,E6[5],qB6);
        qA01 = FMA2(b6,EP[6][0],qA01);
        qA23 = FMA2(b6,EP[6][1],qA23);
        qA45 = FMA2(b6,EP[6][2],qA45);
        qA6  = fmaf(p6,E6[6],qA6);
        u64 q01 = MUL2(ADD2(qA01,qB01), PK(xe[0],xe[1]));
        u64 q23 = MUL2(ADD2(qA23,qB23), PK(xe[2],xe[3]));
        u64 q45 = MUL2(ADD2(qA45,qB45), PK(xe[4],xe[5]));
        float q6 = (qA6 + qB6) * xe[6];
        p01 = M ? q01 : p01;
        p23 = M ? q23 : p23;
        p45 = M ? q45 : p45;
        p6  = M ? q6  : p6;
    };

#define RENORM() do { \
    float a0,a1,a2,a3,a4,a5; \
    UPK(p01,a0,a1); UPK(p23,a2,a3); UPK(p45,a4,a5); \
    float mx = fmaxf(fmaxf(fmaxf(a0,a1), fmaxf(a2,a3)), fmaxf(fmaxf(a4,a5), p6)); \
    int ex = (__float_as_int(mx) >> 23) & 0xFF; \
    float inv = __int_as_float((254 - ex) << 23); \
    xsum += ex - 127; \
    u64 iv = PK(inv, inv); \
    p01 = MUL2(p01,iv); p23 = MUL2(p23,iv); p45 = MUL2(p45,iv); p6 *= inv; } while (0)

    // load 28 floats of 4-step group G via 7x LDS.128, exp them all (MUFU ILP)
#define LOADG(ROWP, G, XE) do { \
    const float4* _q4 = (const float4*)((ROWP) + (G)*28); \
    _Pragma("unroll") \
    for (int c = 0; c < 7; c++) { \
        float4 _v = _q4[c]; \
        XE[4*c+0]=_v.x; XE[4*c+1]=_v.y; XE[4*c+2]=_v.z; XE[4*c+3]=_v.w; \
    } \
    _Pragma("unroll") \
    for (int k = 0; k < 28; k++) XE[k] = __expf(XE[k]); } while (0)

#define PROC8(ROWP, L0v, L1v, M0v, M1v) do { \
    { float xe[28]; LOADG(ROWP, 0, xe); \
      STEP(xe+0,  (ROWP)+0,  (L0v).x, (M0v).x); STEP(xe+7,  (ROWP)+7,  (L0v).y, (M0v).y); \
      STEP(xe+14, (ROWP)+14, (L0v).z, (M0v).z); STEP(xe+21, (ROWP)+21, (L0v).w, (M0v).w); } \
    { float xe[28]; LOADG(ROWP, 1, xe); \
      STEP(xe+0,  (ROWP)+28, (L1v).x, (M1v).x); STEP(xe+7,  (ROWP)+35, (L1v).y, (M1v).y); \
      STEP(xe+14, (ROWP)+42, (L1v).z, (M1v).z); STEP(xe+21, (ROWP)+49, (L1v).w, (M1v).w); } \
    RENORM(); } while (0)

    // ---- prologue ----
    STAGE(0); STAGE(1); STAGE(2);
    int4 lC0 = __ldg(lb4 + 0), lC1 = __ldg(lb4 + 1);
    int4 mC0 = __ldg(mb4 + 0), mC1 = __ldg(mb4 + 1);
    CP_WAIT2(); __syncwarp();

    // ---- init (t=0) ----
    {
        float q[7];
#pragma unroll
        for (int j = 0; j < 7; j++) q[j] = __expf(__ldg(startT + j) + myrow0[j]);
        float mx = q[0];
#pragma unroll
        for (int j = 1; j < 7; j++) mx = fmaxf(mx, q[j]);
        int ex = (__float_as_int(mx) >> 23) & 0xFF;
        float inv = __int_as_float((254 - ex) << 23);
        xsum = ex - 127;
        p01 = PK(q[0]*inv, q[1]*inv);
        p23 = PK(q[2]*inv, q[3]*inv);
        p45 = PK(q[4]*inv, q[5]*inv);
        p6  = q[6]*inv;
        int L0 = lC0.x < 0 ? 0 : lC0.x;
        num = __ldg(startT + L0) + myrow0[L0];
        prev = L0;
    }

    // ---- macro 0: steps 1..7 ----
    {
        float xe[28]; LOADG(myrow0, 0, xe);
        STEP(xe+7,  myrow0+7,  lC0.y, mC0.y);
        STEP(xe+14, myrow0+14, lC0.z, mC0.z);
        STEP(xe+21, myrow0+21, lC0.w, mC0.w);
    }
    {
        float xe[28]; LOADG(myrow0, 1, xe);
        STEP(xe+0,  myrow0+28, lC1.x, mC1.x);
        STEP(xe+7,  myrow0+35, lC1.y, mC1.y);
        STEP(xe+14, myrow0+42, lC1.z, mC1.z);
        STEP(xe+21, myrow0+49, lC1.w, mC1.w);
    }
    RENORM();
    __syncwarp();
    STAGE(3);

    // labels/masks for macro 1
    lC0 = __ldg(lb4 + 2); lC1 = __ldg(lb4 + 3);
    mC0 = __ldg(mb4 + 2); mC1 = __ldg(mb4 + 3);

    // ---- mainloop: macros 1..63 ----
#pragma unroll 1
    for (int m = 1; m < 64; m++) {
        // prefetch next macro's labels/masks a full macro ahead (~1200cyc > DRAM lat)
        int nidx = (m < 63) ? (2*m + 2) : (2*m);   // dummy re-load on last iter
        int4 lN0 = __ldg(lb4 + nidx), lN1 = __ldg(lb4 + nidx + 1);
        int4 mN0 = __ldg(mb4 + nidx), mN1 = __ldg(mb4 + nidx + 1);

        CP_WAIT2(); __syncwarp();
        const float* rowp = (m % 3 == 0) ? myrow0 : (m % 3 == 1) ? myrow1 : myrow2;
        PROC8(rowp, lC0, lC1, mC0, mC1);
        __syncwarp();
        if (m + 3 < 64) STAGE(m + 3);

        lC0 = lN0; lC1 = lN1; mC0 = mN0; mC1 = mN1;
    }

    // ---- finish ----
    float a0,a1,a2,a3,a4,a5;
    UPK(p01,a0,a1); UPK(p23,a2,a3); UPK(p45,a4,a5);
    float acc =        a0 * __expf(__ldg(endT + 0));
    acc = fmaf(a1, __expf(__ldg(endT + 1)), acc);
    acc = fmaf(a2, __expf(__ldg(endT + 2)), acc);
    acc = fmaf(a3, __expf(__ldg(endT + 3)), acc);
    acc = fmaf(a4, __expf(__ldg(endT + 4)), acc);
    acc = fmaf(a5, __expf(__ldg(endT + 5)), acc);
    acc = fmaf(p6, __expf(__ldg(endT + 6)), acc);
    float den  = __logf(acc) + (float)xsum * 0.69314718055994531f;
    float numf = num + __ldg(endT + prev);
    float r = den - numf;

#pragma unroll
    for (int off = 16; off > 0; off >>= 1)
        r += __shfl_xor_sync(0xFFFFFFFFu, r, off);
    if (lane == 0) atomicAdd(out, r);

#undef STAGE
#undef RENORM
#undef LOADG
#undef PROC8
}

extern "C" void kernel_launch(void* const* d_in, const int* in_sizes, int n_in,
                              void* d_out, int out_size)
{
    const float* em     = (const float*)d_in[0];
    const int*   labels = (const int*)  d_in[1];
    const int*   mask   = (const int*)  d_in[2];
    const float* startT = (const float*)d_in[3];
    const float* endT   = (const float*)d_in[4];
    const float* trans  = (const float*)d_in[5];

    cudaMemsetAsync(d_out, 0, sizeof(float));
    crf_fwd_kernel<<<128, 64>>>(em, labels, mask, startT, endT, trans, (float*)d_out);
}